// round 9
// baseline (speedup 1.0000x reference)
#include <cuda_runtime.h>
#include <cooperative_groups.h>
#include <math.h>

namespace cg = cooperative_groups;

// ---------------- problem constants ----------------
#define BB   64      // batch
#define LS   512     // source length
#define LL   128     // law/legal length
#define TT   150     // target length
#define HH   150     // hidden
#define EE   200     // embed
#define G3   450     // 3*HH
#define VV   10000   // target vocab
#define NCH  62      // charges
#define SOS_TOK 2
#define EOS_TOK 1

#define OUT_LOSS   96000000L   // TT*BB*VV
#define OUT_CHARGE 96000001L

// ---------------- scratch (device globals; no allocation allowed) ----------------
__device__ float g_h0[BB*HH];
__device__ float g_emb_src[BB*LS*EE];
__device__ float g_gi[BB*LS*G3];
__device__ float g_enc_outs1[BB*LS*HH];
__device__ float g_chh[BB*HH];
__device__ int   g_legal_toks[BB*LL];
__device__ float g_emb_leg[BB*LL*EE];
__device__ float g_gi_leg[BB*LL*G3];
__device__ float g_legals[BB*LL*HH];
__device__ float g_att[BB*LS*LL];
__device__ float g_ca[BB*LS*HH];
__device__ float g_enc_outs[BB*LS*HH];
__device__ int   g_dec_in[BB*TT];
__device__ float g_emb_dec[BB*TT*EE];
__device__ float g_gi_dec[BB*TT*G3];
__device__ float g_dec_out[BB*TT*HH];
__device__ float g_scores[BB*TT*LS];
__device__ float g_ctx[BB*TT*HH];
__device__ float g_concat[BB*TT*2*HH];
__device__ float g_co[BB*TT*HH];
__device__ float g_nll[BB*TT];
__device__ float g_val[BB*TT];

// ---------------- small helpers ----------------
__device__ __forceinline__ float warp_max(float v){
    #pragma unroll
    for (int o=16;o;o>>=1) v = fmaxf(v, __shfl_xor_sync(0xffffffffu, v, o));
    return v;
}
__device__ __forceinline__ float warp_sum(float v){
    #pragma unroll
    for (int o=16;o;o>>=1) v += __shfl_xor_sync(0xffffffffu, v, o);
    return v;
}
template<int NW>
__device__ __forceinline__ float block_max(float v, float* red){
    v = warp_max(v);
    int w = threadIdx.x >> 5;
    if ((threadIdx.x & 31) == 0) red[w] = v;
    __syncthreads();
    float r = red[0];
    #pragma unroll
    for (int i=1;i<NW;i++) r = fmaxf(r, red[i]);
    __syncthreads();
    return r;
}
template<int NW>
__device__ __forceinline__ float block_sum(float v, float* red){
    v = warp_sum(v);
    int w = threadIdx.x >> 5;
    if ((threadIdx.x & 31) == 0) red[w] = v;
    __syncthreads();
    float r = red[0];
    #pragma unroll
    for (int i=1;i<NW;i++) r += red[i];
    __syncthreads();
    return r;
}

// ---------------- trivial kernels ----------------
__global__ void zero_kernel(float* p, long n){
    long i = (long)blockIdx.x*blockDim.x + threadIdx.x;
    if (i < n) p[i] = 0.f;
}

__global__ void gather_kernel(float* __restrict__ out, const float* __restrict__ table,
                              const int* __restrict__ toks, long nrows, int E){
    long id = (long)blockIdx.x*blockDim.x + threadIdx.x;
    if (id < nrows*(long)E){
        long r = id / E; int j = (int)(id % E);
        out[id] = table[(long)toks[r]*E + j];
    }
}

__global__ void dec_tokens_kernel(const int* __restrict__ tgts, int* __restrict__ dec_in){
    int id = blockIdx.x*blockDim.x + threadIdx.x;
    if (id < BB*TT){
        int b = id / TT, t = id % TT;
        dec_in[id] = (t == 0) ? SOS_TOK : tgts[b*TT + t - 1];
    }
}

__global__ void mean_kernel(const float* __restrict__ outs1, float* __restrict__ chh){
    int b = blockIdx.x; int j = threadIdx.x;
    if (j < HH){
        float s = 0.f;
        for (int t=0;t<LS;t++) s += outs1[((long)b*LS + t)*HH + j];
        chh[b*HH + j] = s * (1.f/LS);
    }
}

__global__ void charge_kernel(const float* __restrict__ chh, const float* __restrict__ Wc,
                              const float* __restrict__ bc, const int* __restrict__ law_tokens,
                              float* __restrict__ out_charge, int* __restrict__ legal_toks){
    int b = blockIdx.x; int tid = threadIdx.x;   // 128 threads
    __shared__ float h[HH];
    __shared__ float sc[NCH];
    __shared__ int cid;
    for (int i=tid;i<HH;i+=128) h[i] = chh[b*HH + i];
    __syncthreads();
    if (tid < NCH){
        float a = bc[tid];
        const float* w = Wc + tid*HH;
        for (int k=0;k<HH;k++) a += h[k]*w[k];
        sc[tid] = a;
        out_charge[b*NCH + tid] = a;
    }
    __syncthreads();
    if (tid == 0){
        int best = 0; float bv = sc[0];
        for (int c=1;c<NCH;c++) if (sc[c] > bv){ bv = sc[c]; best = c; }
        cid = best;
    }
    __syncthreads();
    for (int i=tid;i<LL;i+=128) legal_toks[b*LL + i] = law_tokens[cid*LL + i];
}

// ---------------- persistent GRU sequence kernel, 2 batch rows per cluster ----------------
// 32 clusters of 2 CTAs (grid 64, block 256). Each cluster handles batch rows
// {2c, 2c+1}. Each CTA owns 75 hidden units -> 225 gate rows; the weight row is
// batch-invariant, so each thread computes TWO dot products per step (one per
// batch row). Doubles independent LDS/FFMA streams (hides the 29cyc LDS latency
// that capped issue at 18%) and halves per-row sync cost. cluster.sync per step
// (R6 showed per-thread remote mbarrier arrives are slower).
__global__ void __cluster_dims__(2,1,1) __launch_bounds__(256,1)
gru_seq_kernel(const float* __restrict__ gi, int T,
               const float* __restrict__ Whh, const float* __restrict__ bhh,
               const float* __restrict__ hinit, long hi_stride, long hi_off,
               float* __restrict__ out)
{
    cg::cluster_group cluster = cg::this_cluster();
    int rank = cluster.block_rank();            // 0 or 1
    int b0 = (blockIdx.x >> 1) * 2;             // first batch row of this cluster
    int tid = threadIdx.x;

    __shared__ float h_sm[2][2][152];   // [batch-in-cluster][buffer][pad 152]
    __shared__ float sg[2][3][80];      // [batch-in-cluster][gate][jj]

    int gate = tid / 75;                // 0..2 for matvec threads
    int jj75 = tid - gate*75;
    bool act = tid < 225;
    int jm = rank*75 + jj75;            // matvec hidden index
    int grow = act ? (gate*HH + jm) : 0;

    // combine-thread mapping: tid < 150 -> (cb, jc)
    int cb = tid / 75;                  // batch-in-cluster for combine
    int jj = tid - cb*75;
    int jc = rank*75 + jj;              // combine hidden index

    // register-resident weight row (padded with zeros to 152)
    float w[152];
    if (act){
        #pragma unroll
        for (int k=0;k<150;k++) w[k] = Whh[(long)grow*HH + k];
        w[150] = 0.f; w[151] = 0.f;
    } else {
        #pragma unroll
        for (int k=0;k<152;k++) w[k] = 0.f;
    }
    float bias = act ? bhh[grow] : 0.f;

    // init h buffers for both batch rows
    for (int k=tid;k<2*152;k+=256){
        int bb = k / 152, kk = k % 152;
        h_sm[bb][0][kk] = (kk < HH) ? hinit[(long)(b0+bb)*hi_stride + hi_off + kk] : 0.f;
        h_sm[bb][1][kk] = 0.f;
    }
    float* peer_h = (float*)cluster.map_shared_rank((void*)&h_sm[0][0][0], rank ^ 1);

    cluster.sync();   // init visible before any peer writes

    int p = 0;
    for (int t=0;t<T;t++){
        // prefetch gi for the combine threads (overlaps the matvec)
        float gr = 0.f, gz = 0.f, gn = 0.f;
        if (tid < 150){
            const float* g = gi + ((long)(b0+cb)*T + t)*G3;
            gr = g[jc]; gz = g[HH + jc]; gn = g[2*HH + jc];
        }

        if (act){
            const float4* h4a = (const float4*)&h_sm[0][p][0];
            const float4* h4b = (const float4*)&h_sm[1][p][0];
            float a0=0.f,a1=0.f,a2=0.f,a3=0.f;
            float c0=0.f,c1=0.f,c2=0.f,c3=0.f;
            #pragma unroll
            for (int k4=0;k4<38;k4++){
                float4 hva = h4a[k4];
                float4 hvb = h4b[k4];
                float w0=w[4*k4+0], w1=w[4*k4+1], w2=w[4*k4+2], w3=w[4*k4+3];
                a0 += w0*hva.x; a1 += w1*hva.y; a2 += w2*hva.z; a3 += w3*hva.w;
                c0 += w0*hvb.x; c1 += w1*hvb.y; c2 += w2*hvb.z; c3 += w3*hvb.w;
            }
            sg[0][gate][jj75] = (a0 + a1) + (a2 + a3) + bias;
            sg[1][gate][jj75] = (c0 + c1) + (c2 + c3) + bias;
        }
        __syncthreads();

        if (tid < 150){
            float r = 1.f/(1.f + expf(-(gr + sg[cb][0][jj])));
            float z = 1.f/(1.f + expf(-(gz + sg[cb][1][jj])));
            float n = tanhf(gn + r*sg[cb][2][jj]);
            float hp = h_sm[cb][p][jc];
            float hn = (1.f - z)*n + z*hp;
            h_sm[cb][1-p][jc] = hn;
            peer_h[cb*2*152 + (1-p)*152 + jc] = hn;   // DSMEM write into peer buffer
            out[((long)(b0+cb)*T + t)*HH + jc] = hn;
        }
        cluster.sync();   // peer h writes visible; also orders sg reuse
        p ^= 1;
    }
}

// ---------------- tiled SGEMM: C = A[M,K] x (TRANSB ? B[N,K]^T : B[K,N]) ----------------
// EPI: 0=plain, 1=+bias, 2=tanh(+bias), 3=+residual, 4=+bias with [T,B,V] transposed store
template<int TRANSB, int EPI>
__global__ void gemm_kernel(const float* __restrict__ A, const float* __restrict__ Bm,
                            const float* __restrict__ bias, const float* __restrict__ res,
                            float* __restrict__ C,
                            int M, int N, int K,
                            long sA, long sB, long sC, long sR){
    int z = blockIdx.z;
    A  += (long)z*sA;
    Bm += (long)z*sB;
    C  += (long)z*sC;
    const float* R = (EPI==3) ? (res + (long)z*sR) : res;

    int m0 = blockIdx.y*64, n0 = blockIdx.x*64;
    __shared__ float As[16][68];
    __shared__ float Bs[16][68];
    int tid = threadIdx.x;
    int tx = tid & 15, ty = tid >> 4;
    float c[4][4] = {};

    for (int kk=0; kk<K; kk+=16){
        for (int idx=tid; idx<64*16; idx+=256){
            int i = idx >> 4, k = idx & 15;
            int mi = m0 + i, ki = kk + k;
            As[k][i] = (mi < M && ki < K) ? A[(long)mi*K + ki] : 0.f;
        }
        if (TRANSB){
            for (int idx=tid; idx<64*16; idx+=256){
                int j = idx >> 4, k = idx & 15;
                int nj = n0 + j, ki = kk + k;
                Bs[k][j] = (nj < N && ki < K) ? Bm[(long)nj*K + ki] : 0.f;
            }
        } else {
            for (int idx=tid; idx<64*16; idx+=256){
                int j = idx & 63, k = idx >> 6;
                int nj = n0 + j, ki = kk + k;
                Bs[k][j] = (nj < N && ki < K) ? Bm[(long)ki*N + nj] : 0.f;
            }
        }
        __syncthreads();
        #pragma unroll
        for (int k=0;k<16;k++){
            float4 a4 = *(const float4*)&As[k][ty*4];
            float4 b4 = *(const float4*)&Bs[k][tx*4];
            float af[4] = {a4.x,a4.y,a4.z,a4.w};
            float bf[4] = {b4.x,b4.y,b4.z,b4.w};
            #pragma unroll
            for (int r=0;r<4;r++)
                #pragma unroll
                for (int cc=0;cc<4;cc++)
                    c[r][cc] += af[r]*bf[cc];
        }
        __syncthreads();
    }

    #pragma unroll
    for (int r=0;r<4;r++){
        int i = m0 + ty*4 + r;
        if (i >= M) continue;
        #pragma unroll
        for (int cc=0;cc<4;cc++){
            int j = n0 + tx*4 + cc;
            if (j >= N) continue;
            float v = c[r][cc];
            if (EPI==1 || EPI==2 || EPI==4) v += bias[j];
            if (EPI==2) v = tanhf(v);
            if (EPI==3) v += R[(long)i*N + j];
            if (EPI==4){
                int bb2 = i / TT, tt2 = i % TT;
                C[((long)(tt2*BB + bb2))*N + j] = v;
            } else {
                C[(long)i*N + j] = v;
            }
        }
    }
}

// ---------------- softmaxes ----------------
__global__ void mask_softmax128(float* __restrict__ att){
    long row = blockIdx.x;
    int tid = threadIdx.x;  // 128 threads
    __shared__ float red[4];
    float x = att[row*LL + tid];
    float xm = (x == 0.f) ? -INFINITY : x;
    float M = block_max<4>(xm, red);
    float e = isinf(M) ? 0.f : expf(xm - M);
    float S = block_sum<4>(e, red);
    att[row*LL + tid] = (S > 0.f) ? e / S : 0.f;
}

__global__ void softmax512(float* __restrict__ x){
    long row = blockIdx.x;
    int tid = threadIdx.x;
    __shared__ float red[8];
    float* p = x + row*(long)LS;
    float v0 = p[tid], v1 = p[tid + 256];
    float M = block_max<8>(fmaxf(v0, v1), red);
    float e0 = expf(v0 - M), e1 = expf(v1 - M);
    float S = block_sum<8>(e0 + e1, red);
    float inv = 1.f / S;
    p[tid] = e0*inv; p[tid + 256] = e1*inv;
}

__global__ void concat_kernel(const float* __restrict__ dec_out, const float* __restrict__ ctx,
                              float* __restrict__ cat){
    long id = (long)blockIdx.x*blockDim.x + threadIdx.x;
    long n = (long)BB*TT*2*HH;
    if (id < n){
        long m = id / (2*HH); int j = (int)(id % (2*HH));
        cat[id] = (j < HH) ? dec_out[m*HH + j] : ctx[m*HH + (j - HH)];
    }
}

__global__ void nll_kernel(const float* __restrict__ logits_out, const int* __restrict__ tgts,
                           float* __restrict__ nll, float* __restrict__ validf){
    int row = blockIdx.x;           // b*TT + t
    int tid = threadIdx.x;          // 256 threads
    int b = row / TT, t = row % TT;
    const float* x = logits_out + ((long)(t*BB + b))*VV;
    __shared__ float red[8];
    float m = -INFINITY;
    for (int i=tid;i<VV;i+=256) m = fmaxf(m, x[i]);
    float M = block_max<8>(m, red);
    float s = 0.f;
    for (int i=tid;i<VV;i+=256) s += expf(x[i] - M);
    float S = block_sum<8>(s, red);
    if (tid == 0){
        int tg = tgts[row];
        float v = (tg != EOS_TOK) ? 1.f : 0.f;
        nll[row] = v * ((M + logf(S)) - x[tg]);
        validf[row] = v;
    }
}

__global__ void loss_reduce_kernel(const float* __restrict__ nll, const float* __restrict__ val,
                                   float* __restrict__ out_loss){
    __shared__ float red[8];
    int t = threadIdx.x;  // 256 threads
    float v = 0.f;
    if (t < TT){
        float s = 0.f, c = 0.f;
        for (int b=0;b<BB;b++){ s += nll[b*TT + t]; c += val[b*TT + t]; }
        v = s / fmaxf(c, 1.f);
    }
    float tot = block_sum<8>(v, red);
    if (t == 0) out_loss[0] = tot;
}

// ---------------- host side ----------------
static void launch_gemm(int transb, int epi,
                        const float* A, const float* Bm, const float* bias, const float* res,
                        float* C, int M, int N, int K,
                        long sA, long sB, long sC, long sR, int batch){
    dim3 gr((N + 63)/64, (M + 63)/64, batch);
    dim3 bl(256);
    if (transb){
        if (epi == 0)      gemm_kernel<1,0><<<gr,bl>>>(A,Bm,bias,res,C,M,N,K,sA,sB,sC,sR);
        else if (epi == 1) gemm_kernel<1,1><<<gr,bl>>>(A,Bm,bias,res,C,M,N,K,sA,sB,sC,sR);
        else if (epi == 2) gemm_kernel<1,2><<<gr,bl>>>(A,Bm,bias,res,C,M,N,K,sA,sB,sC,sR);
        else               gemm_kernel<1,4><<<gr,bl>>>(A,Bm,bias,res,C,M,N,K,sA,sB,sC,sR);
    } else {
        if (epi == 0)      gemm_kernel<0,0><<<gr,bl>>>(A,Bm,bias,res,C,M,N,K,sA,sB,sC,sR);
        else               gemm_kernel<0,3><<<gr,bl>>>(A,Bm,bias,res,C,M,N,K,sA,sB,sC,sR);
    }
}

template<typename T> static T* sym(const void* s){
    void* p = nullptr;
    cudaGetSymbolAddress(&p, s);
    return (T*)p;
}

extern "C" void kernel_launch(void* const* d_in, const int* in_sizes, int n_in,
                              void* d_out, int out_size){
    const int*   srcs        = (const int*)  d_in[0];
    const int*   tgts        = (const int*)  d_in[1];
    const int*   law_tokens  = (const int*)  d_in[2];
    const float* src_embed   = (const float*)d_in[3];
    const float* enc_rnn_Wih = (const float*)d_in[4];
    const float* enc_rnn_Whh = (const float*)d_in[5];
    const float* enc_rnn_bih = (const float*)d_in[6];
    const float* enc_rnn_bhh = (const float*)d_in[7];
    const float* enc_gru_Wih = (const float*)d_in[8];
    const float* enc_gru_Whh = (const float*)d_in[9];
    const float* enc_gru_bih = (const float*)d_in[10];
    const float* enc_gru_bhh = (const float*)d_in[11];
    const float* dec_embed   = (const float*)d_in[12];
    const float* dec_rnn_Wih = (const float*)d_in[13];
    const float* dec_rnn_Whh = (const float*)d_in[14];
    const float* dec_rnn_bih = (const float*)d_in[15];
    const float* dec_rnn_bhh = (const float*)d_in[16];
    const float* Ww          = (const float*)d_in[17];
    const float* bw          = (const float*)d_in[18];
    const float* Wp          = (const float*)d_in[19];
    const float* bp          = (const float*)d_in[20];
    const float* Wc          = (const float*)d_in[21];
    const float* bc          = (const float*)d_in[22];
    float* out = (float*)d_out;

    float* h0       = sym<float>(g_h0);
    float* emb_src  = sym<float>(g_emb_src);
    float* gi       = sym<float>(g_gi);
    float* enc1     = sym<float>(g_enc_outs1);
    float* chh      = sym<float>(g_chh);
    int*   leg_toks = sym<int>(g_legal_toks);
    float* emb_leg  = sym<float>(g_emb_leg);
    float* gi_leg   = sym<float>(g_gi_leg);
    float* legals   = sym<float>(g_legals);
    float* att      = sym<float>(g_att);
    float* ca       = sym<float>(g_ca);
    float* enc2     = sym<float>(g_enc_outs);
    int*   dec_in   = sym<int>(g_dec_in);
    float* emb_dec  = sym<float>(g_emb_dec);
    float* gi_dec   = sym<float>(g_gi_dec);
    float* dec_outb = sym<float>(g_dec_out);
    float* scores   = sym<float>(g_scores);
    float* ctx      = sym<float>(g_ctx);
    float* cat      = sym<float>(g_concat);
    float* co       = sym<float>(g_co);
    float* nll      = sym<float>(g_nll);
    float* valf     = sym<float>(g_val);

    // h0 = zeros
    zero_kernel<<<(BB*HH + 255)/256, 256>>>(h0, BB*HH);

    // ---- encoder pass 1 ----
    {
        long n = (long)BB*LS*EE;
        gather_kernel<<<(unsigned)((n + 255)/256), 256>>>(emb_src, src_embed, srcs, (long)BB*LS, EE);
    }
    launch_gemm(1, 1, emb_src, enc_rnn_Wih, enc_rnn_bih, nullptr, gi,
                BB*LS, G3, EE, 0, 0, 0, 0, 1);
    gru_seq_kernel<<<BB, 256>>>(gi, LS, enc_rnn_Whh, enc_rnn_bhh, h0, HH, 0, enc1);

    // ---- charge prediction + legal tokens ----
    mean_kernel<<<BB, 160>>>(enc1, chh);
    charge_kernel<<<BB, 128>>>(chh, Wc, bc, law_tokens, out + OUT_CHARGE, leg_toks);

    // ---- legal encoding (same encoder rnn) ----
    {
        long n = (long)BB*LL*EE;
        gather_kernel<<<(unsigned)((n + 255)/256), 256>>>(emb_leg, src_embed, leg_toks, (long)BB*LL, EE);
    }
    launch_gemm(1, 1, emb_leg, enc_rnn_Wih, enc_rnn_bih, nullptr, gi_leg,
                BB*LL, G3, EE, 0, 0, 0, 0, 1);
    gru_seq_kernel<<<BB, 256>>>(gi_leg, LL, enc_rnn_Whh, enc_rnn_bhh, h0, HH, 0, legals);

    // ---- mask attention: att = enc1 @ legals^T, masked softmax, ca = aw@legals + enc1 ----
    launch_gemm(1, 0, enc1, legals, nullptr, nullptr, att,
                LS, LL, HH, (long)LS*HH, (long)LL*HH, (long)LS*LL, 0, BB);
    mask_softmax128<<<BB*LS, 128>>>(att);
    launch_gemm(0, 3, att, legals, nullptr, enc1, ca,
                LS, HH, LL, (long)LS*LL, (long)LL*HH, (long)LS*HH, (long)LS*HH, BB);

    // ---- encoder pass 2 ----
    launch_gemm(1, 1, ca, enc_gru_Wih, enc_gru_bih, nullptr, gi,
                BB*LS, G3, HH, 0, 0, 0, 0, 1);
    gru_seq_kernel<<<BB, 256>>>(gi, LS, enc_gru_Whh, enc_gru_bhh, h0, HH, 0, enc2);

    // ---- decoder GRU (teacher forcing), h0 = enc2[:,511,:] ----
    dec_tokens_kernel<<<(BB*TT + 255)/256, 256>>>(tgts, dec_in);
    {
        long n = (long)BB*TT*EE;
        gather_kernel<<<(unsigned)((n + 255)/256), 256>>>(emb_dec, dec_embed, dec_in, (long)BB*TT, EE);
    }
    launch_gemm(1, 1, emb_dec, dec_rnn_Wih, dec_rnn_bih, nullptr, gi_dec,
                BB*TT, G3, EE, 0, 0, 0, 0, 1);
    gru_seq_kernel<<<BB, 256>>>(gi_dec, TT, dec_rnn_Whh, dec_rnn_bhh,
                                enc2, (long)LS*HH, (long)(LS-1)*HH, dec_outb);

    // ---- decoder attention ----
    launch_gemm(1, 0, dec_outb, enc2, nullptr, nullptr, scores,
                TT, LS, HH, (long)TT*HH, (long)LS*HH, (long)TT*LS, 0, BB);
    softmax512<<<BB*TT, 256>>>(scores);
    launch_gemm(0, 0, scores, enc2, nullptr, nullptr, ctx,
                TT, HH, LS, (long)TT*LS, (long)LS*HH, (long)TT*HH, 0, BB);

    // ---- co = tanh([dec_out|ctx] @ Ww^T + bw) ----
    {
        long n = (long)BB*TT*2*HH;
        concat_kernel<<<(unsigned)((n + 255)/256), 256>>>(dec_outb, ctx, cat);
    }
    launch_gemm(1, 2, cat, Ww, bw, nullptr, co,
                BB*TT, HH, 2*HH, 0, 0, 0, 0, 1);

    // ---- logits = co @ Wp^T + bp, stored transposed [T,B,1,V] directly into d_out ----
    launch_gemm(1, 4, co, Wp, bp, nullptr, out,
                BB*TT, VV, HH, 0, 0, 0, 0, 1);

    // ---- loss ----
    nll_kernel<<<BB*TT, 256>>>(out, tgts, nll, valf);
    loss_reduce_kernel<<<1, 256>>>(nll, valf, out + OUT_LOSS);
}

// round 11
// speedup vs baseline: 1.1798x; 1.1798x over previous
#include <cuda_runtime.h>
#include <cooperative_groups.h>
#include <math.h>

namespace cg = cooperative_groups;

// ---------------- problem constants ----------------
#define BB   64      // batch
#define LS   512     // source length
#define LL   128     // law/legal length
#define TT   150     // target length
#define HH   150     // hidden
#define EE   200     // embed
#define G3   450     // 3*HH
#define VV   10000   // target vocab
#define NCH  62      // charges
#define SOS_TOK 2
#define EOS_TOK 1

#define OUT_LOSS   96000000L   // TT*BB*VV
#define OUT_CHARGE 96000001L

// ---------------- scratch (device globals; no allocation allowed) ----------------
__device__ float g_h0[BB*HH];
__device__ float g_emb_src[BB*LS*EE];
__device__ float g_gi[BB*LS*G3];
__device__ float g_enc_outs1[BB*LS*HH];
__device__ float g_chh[BB*HH];
__device__ int   g_legal_toks[BB*LL];
__device__ float g_emb_leg[BB*LL*EE];
__device__ float g_gi_leg[BB*LL*G3];
__device__ float g_legals[BB*LL*HH];
__device__ float g_att[BB*LS*LL];
__device__ float g_ca[BB*LS*HH];
__device__ float g_enc_outs[BB*LS*HH];
__device__ int   g_dec_in[BB*TT];
__device__ float g_emb_dec[BB*TT*EE];
__device__ float g_gi_dec[BB*TT*G3];
__device__ float g_dec_out[BB*TT*HH];
__device__ float g_scores[BB*TT*LS];
__device__ float g_ctx[BB*TT*HH];
__device__ float g_concat[BB*TT*2*HH];
__device__ float g_co[BB*TT*HH];
__device__ float g_nll[BB*TT];
__device__ float g_val[BB*TT];

// ---------------- small helpers ----------------
__device__ __forceinline__ float warp_max(float v){
    #pragma unroll
    for (int o=16;o;o>>=1) v = fmaxf(v, __shfl_xor_sync(0xffffffffu, v, o));
    return v;
}
__device__ __forceinline__ float warp_sum(float v){
    #pragma unroll
    for (int o=16;o;o>>=1) v += __shfl_xor_sync(0xffffffffu, v, o);
    return v;
}
template<int NW>
__device__ __forceinline__ float block_max(float v, float* red){
    v = warp_max(v);
    int w = threadIdx.x >> 5;
    if ((threadIdx.x & 31) == 0) red[w] = v;
    __syncthreads();
    float r = red[0];
    #pragma unroll
    for (int i=1;i<NW;i++) r = fmaxf(r, red[i]);
    __syncthreads();
    return r;
}
template<int NW>
__device__ __forceinline__ float block_sum(float v, float* red){
    v = warp_sum(v);
    int w = threadIdx.x >> 5;
    if ((threadIdx.x & 31) == 0) red[w] = v;
    __syncthreads();
    float r = red[0];
    #pragma unroll
    for (int i=1;i<NW;i++) r += red[i];
    __syncthreads();
    return r;
}

// ---------------- trivial kernels ----------------
__global__ void zero_kernel(float* p, long n){
    long i = (long)blockIdx.x*blockDim.x + threadIdx.x;
    if (i < n) p[i] = 0.f;
}

__global__ void gather_kernel(float* __restrict__ out, const float* __restrict__ table,
                              const int* __restrict__ toks, long nrows, int E){
    long id = (long)blockIdx.x*blockDim.x + threadIdx.x;
    if (id < nrows*(long)E){
        long r = id / E; int j = (int)(id % E);
        out[id] = table[(long)toks[r]*E + j];
    }
}

__global__ void dec_tokens_kernel(const int* __restrict__ tgts, int* __restrict__ dec_in){
    int id = blockIdx.x*blockDim.x + threadIdx.x;
    if (id < BB*TT){
        int b = id / TT, t = id % TT;
        dec_in[id] = (t == 0) ? SOS_TOK : tgts[b*TT + t - 1];
    }
}

__global__ void mean_kernel(const float* __restrict__ outs1, float* __restrict__ chh){
    int b = blockIdx.x; int j = threadIdx.x;
    if (j < HH){
        float s = 0.f;
        for (int t=0;t<LS;t++) s += outs1[((long)b*LS + t)*HH + j];
        chh[b*HH + j] = s * (1.f/LS);
    }
}

__global__ void charge_kernel(const float* __restrict__ chh, const float* __restrict__ Wc,
                              const float* __restrict__ bc, const int* __restrict__ law_tokens,
                              float* __restrict__ out_charge, int* __restrict__ legal_toks){
    int b = blockIdx.x; int tid = threadIdx.x;   // 128 threads
    __shared__ float h[HH];
    __shared__ float sc[NCH];
    __shared__ int cid;
    for (int i=tid;i<HH;i+=128) h[i] = chh[b*HH + i];
    __syncthreads();
    if (tid < NCH){
        float a = bc[tid];
        const float* w = Wc + tid*HH;
        for (int k=0;k<HH;k++) a += h[k]*w[k];
        sc[tid] = a;
        out_charge[b*NCH + tid] = a;
    }
    __syncthreads();
    if (tid == 0){
        int best = 0; float bv = sc[0];
        for (int c=1;c<NCH;c++) if (sc[c] > bv){ bv = sc[c]; best = c; }
        cid = best;
    }
    __syncthreads();
    for (int i=tid;i<LL;i+=128) legal_toks[b*LL + i] = law_tokens[cid*LL + i];
}

// ---------------- persistent GRU sequence kernel: 4-CTA cluster per batch row --------
// Grid 4*BB (64 clusters of 4 CTAs), block 128, __launch_bounds__(128,2) so TWO CTAs
// from two DIFFERENT clusters co-reside per SM: one cluster's per-step sync/stall
// latency is hidden by the other's matvec (R9 showed per-step marginal work is cheap;
// the fixed ~2100cyc sync+stall dominates — overlap it across independent clusters).
// Each CTA owns hidden slice [rank*38, rank*38+nj) (nj=38,38,38,36) -> <=114 gate rows,
// weight rows register-resident. h (all 150) replicated per CTA, double-buffered;
// combine threads broadcast their hn to all 4 CTAs via mapped DSMEM pointers.
// One cluster.sync per step (proven protocol; per-thread remote mbar arrives were worse).
__global__ void __cluster_dims__(4,1,1) __launch_bounds__(128,2)
gru_seq_kernel(const float* __restrict__ gi, int T,
               const float* __restrict__ Whh, const float* __restrict__ bhh,
               const float* __restrict__ hinit, long hi_stride, long hi_off,
               float* __restrict__ out)
{
    cg::cluster_group cluster = cg::this_cluster();
    int rank = cluster.block_rank();            // 0..3
    int b = blockIdx.x >> 2;                    // batch row
    int tid = threadIdx.x;

    __shared__ float h_sm[2][152];   // full h, padded for float4
    __shared__ float sg[3][40];      // this CTA's gate partials

    int nj = (rank < 3) ? 38 : 36;   // 150 = 38+38+38+36
    int gate = tid / 38;             // 0..2 for tid<114
    int jj = tid - gate*38;
    bool act = (tid < 114) && (jj < nj);
    int j = rank*38 + jj;            // gate-row hidden index
    int grow = act ? (gate*HH + j) : 0;

    // register-resident weight row (padded with zeros to 152)
    float w[152];
    if (act){
        #pragma unroll
        for (int k=0;k<150;k++) w[k] = Whh[(long)grow*HH + k];
        w[150] = 0.f; w[151] = 0.f;
    } else {
        #pragma unroll
        for (int k=0;k<152;k++) w[k] = 0.f;
    }
    float bias = act ? bhh[grow] : 0.f;

    // init h buffers
    for (int k=tid;k<152;k+=128){
        h_sm[0][k] = (k < HH) ? hinit[(long)b*hi_stride + hi_off + k] : 0.f;
        h_sm[1][k] = 0.f;
    }

    // mapped h pointers for all 4 CTAs of the cluster (incl. self)
    float* ph0 = (float*)cluster.map_shared_rank((void*)&h_sm[0][0], 0);
    float* ph1 = (float*)cluster.map_shared_rank((void*)&h_sm[0][0], 1);
    float* ph2 = (float*)cluster.map_shared_rank((void*)&h_sm[0][0], 2);
    float* ph3 = (float*)cluster.map_shared_rank((void*)&h_sm[0][0], 3);

    cluster.sync();   // init visible before any peer writes

    int p = 0;
    for (int t=0;t<T;t++){
        // prefetch gi for the combine threads (overlaps the matvec)
        float gr = 0.f, gz = 0.f, gn = 0.f;
        int jc = rank*38 + tid;
        if (tid < nj){
            const float* g = gi + ((long)b*T + t)*G3;
            gr = g[jc]; gz = g[HH + jc]; gn = g[2*HH + jc];
        }

        if (tid < 114){   // padded rows compute zeros into unused sg slots
            const float4* h4 = (const float4*)&h_sm[p][0];
            float a0 = 0.f, a1 = 0.f, a2 = 0.f, a3 = 0.f;
            #pragma unroll
            for (int k4=0;k4<38;k4++){
                float4 hv = h4[k4];
                a0 += w[4*k4+0]*hv.x;
                a1 += w[4*k4+1]*hv.y;
                a2 += w[4*k4+2]*hv.z;
                a3 += w[4*k4+3]*hv.w;
            }
            sg[gate][jj] = (a0 + a1) + (a2 + a3) + bias;
        }
        __syncthreads();

        if (tid < nj){
            float r = 1.f/(1.f + expf(-(gr + sg[0][tid])));
            float z = 1.f/(1.f + expf(-(gz + sg[1][tid])));
            float n = tanhf(gn + r*sg[2][tid]);
            float hp = h_sm[p][jc];
            float hn = (1.f - z)*n + z*hp;
            int dst = (1-p)*152 + jc;
            ph0[dst] = hn;                      // broadcast to all 4 CTAs (DSMEM)
            ph1[dst] = hn;
            ph2[dst] = hn;
            ph3[dst] = hn;
            out[((long)b*T + t)*HH + jc] = hn;
        }
        cluster.sync();   // all CTAs' h slices visible everywhere; orders sg reuse
        p ^= 1;
    }
}

// ---------------- tiled SGEMM: C = A[M,K] x (TRANSB ? B[N,K]^T : B[K,N]) ----------------
// EPI: 0=plain, 1=+bias, 2=tanh(+bias), 3=+residual, 4=+bias with [T,B,V] transposed store
template<int TRANSB, int EPI>
__global__ void gemm_kernel(const float* __restrict__ A, const float* __restrict__ Bm,
                            const float* __restrict__ bias, const float* __restrict__ res,
                            float* __restrict__ C,
                            int M, int N, int K,
                            long sA, long sB, long sC, long sR){
    int z = blockIdx.z;
    A  += (long)z*sA;
    Bm += (long)z*sB;
    C  += (long)z*sC;
    const float* R = (EPI==3) ? (res + (long)z*sR) : res;

    int m0 = blockIdx.y*64, n0 = blockIdx.x*64;
    __shared__ float As[16][68];
    __shared__ float Bs[16][68];
    int tid = threadIdx.x;
    int tx = tid & 15, ty = tid >> 4;
    float c[4][4] = {};

    for (int kk=0; kk<K; kk+=16){
        for (int idx=tid; idx<64*16; idx+=256){
            int i = idx >> 4, k = idx & 15;
            int mi = m0 + i, ki = kk + k;
            As[k][i] = (mi < M && ki < K) ? A[(long)mi*K + ki] : 0.f;
        }
        if (TRANSB){
            for (int idx=tid; idx<64*16; idx+=256){
                int j = idx >> 4, k = idx & 15;
                int nj = n0 + j, ki = kk + k;
                Bs[k][j] = (nj < N && ki < K) ? Bm[(long)nj*K + ki] : 0.f;
            }
        } else {
            for (int idx=tid; idx<64*16; idx+=256){
                int j = idx & 63, k = idx >> 6;
                int nj = n0 + j, ki = kk + k;
                Bs[k][j] = (nj < N && ki < K) ? Bm[(long)ki*N + nj] : 0.f;
            }
        }
        __syncthreads();
        #pragma unroll
        for (int k=0;k<16;k++){
            float4 a4 = *(const float4*)&As[k][ty*4];
            float4 b4 = *(const float4*)&Bs[k][tx*4];
            float af[4] = {a4.x,a4.y,a4.z,a4.w};
            float bf[4] = {b4.x,b4.y,b4.z,b4.w};
            #pragma unroll
            for (int r=0;r<4;r++)
                #pragma unroll
                for (int cc=0;cc<4;cc++)
                    c[r][cc] += af[r]*bf[cc];
        }
        __syncthreads();
    }

    #pragma unroll
    for (int r=0;r<4;r++){
        int i = m0 + ty*4 + r;
        if (i >= M) continue;
        #pragma unroll
        for (int cc=0;cc<4;cc++){
            int j = n0 + tx*4 + cc;
            if (j >= N) continue;
            float v = c[r][cc];
            if (EPI==1 || EPI==2 || EPI==4) v += bias[j];
            if (EPI==2) v = tanhf(v);
            if (EPI==3) v += R[(long)i*N + j];
            if (EPI==4){
                int bb2 = i / TT, tt2 = i % TT;
                C[((long)(tt2*BB + bb2))*N + j] = v;
            } else {
                C[(long)i*N + j] = v;
            }
        }
    }
}

// ---------------- softmaxes ----------------
__global__ void mask_softmax128(float* __restrict__ att){
    long row = blockIdx.x;
    int tid = threadIdx.x;  // 128 threads
    __shared__ float red[4];
    float x = att[row*LL + tid];
    float xm = (x == 0.f) ? -INFINITY : x;
    float M = block_max<4>(xm, red);
    float e = isinf(M) ? 0.f : expf(xm - M);
    float S = block_sum<4>(e, red);
    att[row*LL + tid] = (S > 0.f) ? e / S : 0.f;
}

__global__ void softmax512(float* __restrict__ x){
    long row = blockIdx.x;
    int tid = threadIdx.x;
    __shared__ float red[8];
    float* p = x + row*(long)LS;
    float v0 = p[tid], v1 = p[tid + 256];
    float M = block_max<8>(fmaxf(v0, v1), red);
    float e0 = expf(v0 - M), e1 = expf(v1 - M);
    float S = block_sum<8>(e0 + e1, red);
    float inv = 1.f / S;
    p[tid] = e0*inv; p[tid + 256] = e1*inv;
}

__global__ void concat_kernel(const float* __restrict__ dec_out, const float* __restrict__ ctx,
                              float* __restrict__ cat){
    long id = (long)blockIdx.x*blockDim.x + threadIdx.x;
    long n = (long)BB*TT*2*HH;
    if (id < n){
        long m = id / (2*HH); int j = (int)(id % (2*HH));
        cat[id] = (j < HH) ? dec_out[m*HH + j] : ctx[m*HH + (j - HH)];
    }
}

__global__ void nll_kernel(const float* __restrict__ logits_out, const int* __restrict__ tgts,
                           float* __restrict__ nll, float* __restrict__ validf){
    int row = blockIdx.x;           // b*TT + t
    int tid = threadIdx.x;          // 256 threads
    int b = row / TT, t = row % TT;
    const float* x = logits_out + ((long)(t*BB + b))*VV;
    __shared__ float red[8];
    float m = -INFINITY;
    for (int i=tid;i<VV;i+=256) m = fmaxf(m, x[i]);
    float M = block_max<8>(m, red);
    float s = 0.f;
    for (int i=tid;i<VV;i+=256) s += expf(x[i] - M);
    float S = block_sum<8>(s, red);
    if (tid == 0){
        int tg = tgts[row];
        float v = (tg != EOS_TOK) ? 1.f : 0.f;
        nll[row] = v * ((M + logf(S)) - x[tg]);
        validf[row] = v;
    }
}

__global__ void loss_reduce_kernel(const float* __restrict__ nll, const float* __restrict__ val,
                                   float* __restrict__ out_loss){
    __shared__ float red[8];
    int t = threadIdx.x;  // 256 threads
    float v = 0.f;
    if (t < TT){
        float s = 0.f, c = 0.f;
        for (int b=0;b<BB;b++){ s += nll[b*TT + t]; c += val[b*TT + t]; }
        v = s / fmaxf(c, 1.f);
    }
    float tot = block_sum<8>(v, red);
    if (t == 0) out_loss[0] = tot;
}

// ---------------- host side ----------------
static void launch_gemm(int transb, int epi,
                        const float* A, const float* Bm, const float* bias, const float* res,
                        float* C, int M, int N, int K,
                        long sA, long sB, long sC, long sR, int batch){
    dim3 gr((N + 63)/64, (M + 63)/64, batch);
    dim3 bl(256);
    if (transb){
        if (epi == 0)      gemm_kernel<1,0><<<gr,bl>>>(A,Bm,bias,res,C,M,N,K,sA,sB,sC,sR);
        else if (epi == 1) gemm_kernel<1,1><<<gr,bl>>>(A,Bm,bias,res,C,M,N,K,sA,sB,sC,sR);
        else if (epi == 2) gemm_kernel<1,2><<<gr,bl>>>(A,Bm,bias,res,C,M,N,K,sA,sB,sC,sR);
        else               gemm_kernel<1,4><<<gr,bl>>>(A,Bm,bias,res,C,M,N,K,sA,sB,sC,sR);
    } else {
        if (epi == 0)      gemm_kernel<0,0><<<gr,bl>>>(A,Bm,bias,res,C,M,N,K,sA,sB,sC,sR);
        else               gemm_kernel<0,3><<<gr,bl>>>(A,Bm,bias,res,C,M,N,K,sA,sB,sC,sR);
    }
}

template<typename T> static T* sym(const void* s){
    void* p = nullptr;
    cudaGetSymbolAddress(&p, s);
    return (T*)p;
}

extern "C" void kernel_launch(void* const* d_in, const int* in_sizes, int n_in,
                              void* d_out, int out_size){
    const int*   srcs        = (const int*)  d_in[0];
    const int*   tgts        = (const int*)  d_in[1];
    const int*   law_tokens  = (const int*)  d_in[2];
    const float* src_embed   = (const float*)d_in[3];
    const float* enc_rnn_Wih = (const float*)d_in[4];
    const float* enc_rnn_Whh = (const float*)d_in[5];
    const float* enc_rnn_bih = (const float*)d_in[6];
    const float* enc_rnn_bhh = (const float*)d_in[7];
    const float* enc_gru_Wih = (const float*)d_in[8];
    const float* enc_gru_Whh = (const float*)d_in[9];
    const float* enc_gru_bih = (const float*)d_in[10];
    const float* enc_gru_bhh = (const float*)d_in[11];
    const float* dec_embed   = (const float*)d_in[12];
    const float* dec_rnn_Wih = (const float*)d_in[13];
    const float* dec_rnn_Whh = (const float*)d_in[14];
    const float* dec_rnn_bih = (const float*)d_in[15];
    const float* dec_rnn_bhh = (const float*)d_in[16];
    const float* Ww          = (const float*)d_in[17];
    const float* bw          = (const float*)d_in[18];
    const float* Wp          = (const float*)d_in[19];
    const float* bp          = (const float*)d_in[20];
    const float* Wc          = (const float*)d_in[21];
    const float* bc          = (const float*)d_in[22];
    float* out = (float*)d_out;

    float* h0       = sym<float>(g_h0);
    float* emb_src  = sym<float>(g_emb_src);
    float* gi       = sym<float>(g_gi);
    float* enc1     = sym<float>(g_enc_outs1);
    float* chh      = sym<float>(g_chh);
    int*   leg_toks = sym<int>(g_legal_toks);
    float* emb_leg  = sym<float>(g_emb_leg);
    float* gi_leg   = sym<float>(g_gi_leg);
    float* legals   = sym<float>(g_legals);
    float* att      = sym<float>(g_att);
    float* ca       = sym<float>(g_ca);
    float* enc2     = sym<float>(g_enc_outs);
    int*   dec_in   = sym<int>(g_dec_in);
    float* emb_dec  = sym<float>(g_emb_dec);
    float* gi_dec   = sym<float>(g_gi_dec);
    float* dec_outb = sym<float>(g_dec_out);
    float* scores   = sym<float>(g_scores);
    float* ctx      = sym<float>(g_ctx);
    float* cat      = sym<float>(g_concat);
    float* co       = sym<float>(g_co);
    float* nll      = sym<float>(g_nll);
    float* valf     = sym<float>(g_val);

    // h0 = zeros
    zero_kernel<<<(BB*HH + 255)/256, 256>>>(h0, BB*HH);

    // ---- encoder pass 1 ----
    {
        long n = (long)BB*LS*EE;
        gather_kernel<<<(unsigned)((n + 255)/256), 256>>>(emb_src, src_embed, srcs, (long)BB*LS, EE);
    }
    launch_gemm(1, 1, emb_src, enc_rnn_Wih, enc_rnn_bih, nullptr, gi,
                BB*LS, G3, EE, 0, 0, 0, 0, 1);
    gru_seq_kernel<<<4*BB, 128>>>(gi, LS, enc_rnn_Whh, enc_rnn_bhh, h0, HH, 0, enc1);

    // ---- charge prediction + legal tokens ----
    mean_kernel<<<BB, 160>>>(enc1, chh);
    charge_kernel<<<BB, 128>>>(chh, Wc, bc, law_tokens, out + OUT_CHARGE, leg_toks);

    // ---- legal encoding (same encoder rnn) ----
    {
        long n = (long)BB*LL*EE;
        gather_kernel<<<(unsigned)((n + 255)/256), 256>>>(emb_leg, src_embed, leg_toks, (long)BB*LL, EE);
    }
    launch_gemm(1, 1, emb_leg, enc_rnn_Wih, enc_rnn_bih, nullptr, gi_leg,
                BB*LL, G3, EE, 0, 0, 0, 0, 1);
    gru_seq_kernel<<<4*BB, 128>>>(gi_leg, LL, enc_rnn_Whh, enc_rnn_bhh, h0, HH, 0, legals);

    // ---- mask attention: att = enc1 @ legals^T, masked softmax, ca = aw@legals + enc1 ----
    launch_gemm(1, 0, enc1, legals, nullptr, nullptr, att,
                LS, LL, HH, (long)LS*HH, (long)LL*HH, (long)LS*LL, 0, BB);
    mask_softmax128<<<BB*LS, 128>>>(att);
    launch_gemm(0, 3, att, legals, nullptr, enc1, ca,
                LS, HH, LL, (long)LS*LL, (long)LL*HH, (long)LS*HH, (long)LS*HH, BB);

    // ---- encoder pass 2 ----
    launch_gemm(1, 1, ca, enc_gru_Wih, enc_gru_bih, nullptr, gi,
                BB*LS, G3, HH, 0, 0, 0, 0, 1);
    gru_seq_kernel<<<4*BB, 128>>>(gi, LS, enc_gru_Whh, enc_gru_bhh, h0, HH, 0, enc2);

    // ---- decoder GRU (teacher forcing), h0 = enc2[:,511,:] ----
    dec_tokens_kernel<<<(BB*TT + 255)/256, 256>>>(tgts, dec_in);
    {
        long n = (long)BB*TT*EE;
        gather_kernel<<<(unsigned)((n + 255)/256), 256>>>(emb_dec, dec_embed, dec_in, (long)BB*TT, EE);
    }
    launch_gemm(1, 1, emb_dec, dec_rnn_Wih, dec_rnn_bih, nullptr, gi_dec,
                BB*TT, G3, EE, 0, 0, 0, 0, 1);
    gru_seq_kernel<<<4*BB, 128>>>(gi_dec, TT, dec_rnn_Whh, dec_rnn_bhh,
                                  enc2, (long)LS*HH, (long)(LS-1)*HH, dec_outb);

    // ---- decoder attention ----
    launch_gemm(1, 0, dec_outb, enc2, nullptr, nullptr, scores,
                TT, LS, HH, (long)TT*HH, (long)LS*HH, (long)TT*LS, 0, BB);
    softmax512<<<BB*TT, 256>>>(scores);
    launch_gemm(0, 0, scores, enc2, nullptr, nullptr, ctx,
                TT, HH, LS, (long)TT*LS, (long)LS*HH, (long)TT*HH, 0, BB);

    // ---- co = tanh([dec_out|ctx] @ Ww^T + bw) ----
    {
        long n = (long)BB*TT*2*HH;
        concat_kernel<<<(unsigned)((n + 255)/256), 256>>>(dec_outb, ctx, cat);
    }
    launch_gemm(1, 2, cat, Ww, bw, nullptr, co,
                BB*TT, HH, 2*HH, 0, 0, 0, 0, 1);

    // ---- logits = co @ Wp^T + bp, stored transposed [T,B,1,V] directly into d_out ----
    launch_gemm(1, 4, co, Wp, bp, nullptr, out,
                BB*TT, VV, HH, 0, 0, 0, 0, 1);

    // ---- loss ----
    nll_kernel<<<BB*TT, 256>>>(out, tgts, nll, valf);
    loss_reduce_kernel<<<1, 256>>>(nll, valf, out + OUT_LOSS);
}